// round 6
// baseline (speedup 1.0000x reference)
#include <cuda_runtime.h>
#include <cuda_bf16.h>
#include <math.h>

#define Bb  2
#define Ss  2048
#define Dd  1024
#define Hh  16
#define HDd 64
#define Ff  4096
#define Ee  8
#define Tt  4096          // B*S
#define EPSf 1e-5f

// ----------------------------- scratch (static device memory) ---------------
__device__ float g_h1 [(size_t)Tt * Dd];
__device__ float g_q  [(size_t)Tt * Dd];
__device__ float g_k  [(size_t)Tt * Dd];
__device__ float g_v  [(size_t)Tt * Dd];
__device__ float g_ao [(size_t)Tt * Dd];
__device__ float g_h  [(size_t)Tt * Dd];
__device__ float g_h2 [(size_t)Tt * Dd];
__device__ float g_act[134217728];          // 8 experts * 4096 rows * 4096 (512MB)
__device__ int   g_idx[Ee * Tt];
__device__ float g_wgt[Ee * Tt];
__device__ int   g_cnt[Ee];

// ----------------------------- utility kernels ------------------------------
__global__ void k_zero() {
    if (threadIdx.x < Ee) g_cnt[threadIdx.x] = 0;
}

// rmsnorm: mode 0: in = xin, out = g_h1 ; mode 1: in = g_h, out = g_h2
__global__ void __launch_bounds__(256) k_rms(const float* __restrict__ xin,
                                             const float* __restrict__ w, int mode) {
    int t = blockIdx.x, tid = threadIdx.x;
    const float* in = mode ? g_h : xin;
    float* outp     = mode ? g_h2 : g_h1;
    float4 v = ((const float4*)(in + (size_t)t * Dd))[tid];
    float s = v.x*v.x + v.y*v.y + v.z*v.z + v.w*v.w;
    #pragma unroll
    for (int off = 16; off; off >>= 1) s += __shfl_xor_sync(0xffffffffu, s, off);
    __shared__ float red[8];
    __shared__ float rs_s;
    if ((tid & 31) == 0) red[tid >> 5] = s;
    __syncthreads();
    if (tid == 0) {
        float tot = 0.f;
        #pragma unroll
        for (int i = 0; i < 8; i++) tot += red[i];
        rs_s = rsqrtf(tot / (float)Dd + EPSf);
    }
    __syncthreads();
    float rs = rs_s;
    float4 wv = ((const float4*)w)[tid];
    float4 ov = make_float4(v.x*rs*wv.x, v.y*rs*wv.y, v.z*rs*wv.z, v.w*rs*wv.w);
    ((float4*)(outp + (size_t)t * Dd))[tid] = ov;
}

// ----------------------------- generic 128x128x16 fp32 GEMM tile ------------
// A accessed via per-thread row pointer (gathered rows supported by caller).
__device__ __forceinline__ void gemm_tile(const float* __restrict__ aPtr,
                                          const float* __restrict__ B, int ldb,
                                          int n0, int Kdim,
                                          float (&acc)[8][8],
                                          float* __restrict__ As,
                                          float* __restrict__ Bs) {
    const int tid  = threadIdx.x;
    const int acol = (tid & 1) * 8;
    const int arow = tid >> 1;
    const int brow = tid >> 4;
    const int bcol = (tid & 15) * 8;
    const int tm   = (tid >> 4) * 8;
    const int tn   = (tid & 15) * 8;
    const float* bPtr = B + (size_t)brow * ldb + n0 + bcol;

    for (int k0 = 0; k0 < Kdim; k0 += 16) {
        float4 a0, a1;
        if (aPtr) {
            a0 = *(const float4*)(aPtr + k0 + acol);
            a1 = *(const float4*)(aPtr + k0 + acol + 4);
        } else {
            a0 = make_float4(0.f, 0.f, 0.f, 0.f); a1 = a0;
        }
        float4 b0 = *(const float4*)(bPtr + (size_t)k0 * ldb);
        float4 b1 = *(const float4*)(bPtr + (size_t)k0 * ldb + 4);
        As[(acol+0)*128 + arow] = a0.x;  As[(acol+1)*128 + arow] = a0.y;
        As[(acol+2)*128 + arow] = a0.z;  As[(acol+3)*128 + arow] = a0.w;
        As[(acol+4)*128 + arow] = a1.x;  As[(acol+5)*128 + arow] = a1.y;
        As[(acol+6)*128 + arow] = a1.z;  As[(acol+7)*128 + arow] = a1.w;
        *(float4*)(Bs + brow*128 + bcol)     = b0;
        *(float4*)(Bs + brow*128 + bcol + 4) = b1;
        __syncthreads();
        #pragma unroll
        for (int kk = 0; kk < 16; kk++) {
            float af[8], bf[8];
            #pragma unroll
            for (int i = 0; i < 8; i++) af[i] = As[kk*128 + tm + i];
            #pragma unroll
            for (int j = 0; j < 8; j++) bf[j] = Bs[kk*128 + tn + j];
            #pragma unroll
            for (int i = 0; i < 8; i++)
                #pragma unroll
                for (int j = 0; j < 8; j++)
                    acc[i][j] = fmaf(af[i], bf[j], acc[i][j]);
        }
        __syncthreads();
    }
}

#define ZERO_ACC(acc) do {                    \
    _Pragma("unroll")                         \
    for (int _i = 0; _i < 8; _i++)            \
        _Pragma("unroll")                     \
        for (int _j = 0; _j < 8; _j++) acc[_i][_j] = 0.f; } while (0)

// ----------------------------- QKV projection -------------------------------
__global__ void __launch_bounds__(256) k_qkv(const float* __restrict__ wq,
                                             const float* __restrict__ wk,
                                             const float* __restrict__ wv) {
    __shared__ float sm[4096];
    const float* W = (blockIdx.z == 0) ? wq : (blockIdx.z == 1) ? wk : wv;
    float* O       = (blockIdx.z == 0) ? g_q : (blockIdx.z == 1) ? g_k : g_v;
    int m0 = blockIdx.y * 128, n0 = blockIdx.x * 128;
    float acc[8][8]; ZERO_ACC(acc);
    const float* aPtr = g_h1 + (size_t)(m0 + (threadIdx.x >> 1)) * Dd;
    gemm_tile(aPtr, W, Dd, n0, Dd, acc, sm, sm + 2048);
    int tm = (threadIdx.x >> 4) * 8, tn = (threadIdx.x & 15) * 8;
    #pragma unroll
    for (int i = 0; i < 8; i++) {
        size_t base = (size_t)(m0 + tm + i) * Dd + n0 + tn;
        *(float4*)(O + base)     = make_float4(acc[i][0], acc[i][1], acc[i][2], acc[i][3]);
        *(float4*)(O + base + 4) = make_float4(acc[i][4], acc[i][5], acc[i][6], acc[i][7]);
    }
}

// ----------------------------- RoPE (interleaved) ----------------------------
__global__ void __launch_bounds__(256) k_rope(const int* __restrict__ pos) {
    size_t i = (size_t)blockIdx.x * blockDim.x + threadIdx.x;   // T*H*32 threads
    int pi = (int)(i & 31);
    size_t rest = i >> 5;
    int h = (int)(rest & 15);
    size_t t = rest >> 4;
    float inv = 1.0f / powf(10000.0f, (2.0f * (float)pi) / 64.0f);
    float ang = (float)pos[t] * inv;
    float c = cosf(ang), s = sinf(ang);
    size_t base = t * Dd + (size_t)h * HDd + (size_t)pi * 2;
    float x1 = g_q[base], x2 = g_q[base + 1];
    g_q[base]     = x1 * c - x2 * s;
    g_q[base + 1] = x1 * s + x2 * c;
    x1 = g_k[base]; x2 = g_k[base + 1];
    g_k[base]     = x1 * c - x2 * s;
    g_k[base + 1] = x1 * s + x2 * c;
}

// ----------------------------- causal flash attention -----------------------
__global__ void __launch_bounds__(256) k_attn() {
    extern __shared__ float sm[];
    float* Qt = sm;            // [64][64] transposed: Qt[d][r]
    float* Kt = sm + 4096;     // [64][64] transposed: Kt[d][c]
    float* Vs = sm + 8192;     // [64][64] natural:    Vs[k][d]
    float* Pt = sm + 12288;    // [64][64] transposed: Pt[k][r]
    float* Ms = sm + 16384;    // [64]
    float* Ls = Ms + 64;       // [64]

    int tid = threadIdx.x;
    int bh = blockIdx.y;
    int b = bh >> 4, h = bh & 15;
    int q0 = blockIdx.x * 64;
    size_t headoff = (size_t)b * Ss * Dd + (size_t)h * HDd;
    const float* qb = g_q + headoff;
    const float* kb = g_k + headoff;
    const float* vb = g_v + headoff;

    #pragma unroll
    for (int u = 0; u < 4; u++) {
        int qi = u * 256 + tid;
        int r = qi >> 4, dq = (qi & 15) * 4;
        float4 t4 = *(const float4*)(qb + (size_t)(q0 + r) * Dd + dq);
        Qt[(dq+0)*64 + r] = t4.x; Qt[(dq+1)*64 + r] = t4.y;
        Qt[(dq+2)*64 + r] = t4.z; Qt[(dq+3)*64 + r] = t4.w;
    }
    if (tid < 64) { Ms[tid] = -1e30f; Ls[tid] = 0.f; }

    int tr = tid >> 4, tc = tid & 15;
    int r0 = tr * 4, c0 = tc * 4;
    float acco[4][4];
    #pragma unroll
    for (int i = 0; i < 4; i++)
        #pragma unroll
        for (int j = 0; j < 4; j++) acco[i][j] = 0.f;
    __syncthreads();

    for (int kt = 0; kt <= blockIdx.x; kt++) {
        int k0 = kt * 64;
        #pragma unroll
        for (int u = 0; u < 4; u++) {
            int qi = u * 256 + tid;
            int r = qi >> 4, dq = (qi & 15) * 4;
            float4 t4 = *(const float4*)(kb + (size_t)(k0 + r) * Dd + dq);
            Kt[(dq+0)*64 + r] = t4.x; Kt[(dq+1)*64 + r] = t4.y;
            Kt[(dq+2)*64 + r] = t4.z; Kt[(dq+3)*64 + r] = t4.w;
            float4 v4 = *(const float4*)(vb + (size_t)(k0 + r) * Dd + dq);
            *(float4*)(Vs + r * 64 + dq) = v4;
        }
        __syncthreads();

        float s[4][4];
        #pragma unroll
        for (int i = 0; i < 4; i++)
            #pragma unroll
            for (int j = 0; j < 4; j++) s[i][j] = 0.f;
        #pragma unroll 8
        for (int d = 0; d < 64; d++) {
            float af[4], bf[4];
            #pragma unroll
            for (int i = 0; i < 4; i++) af[i] = Qt[d*64 + r0 + i];
            #pragma unroll
            for (int j = 0; j < 4; j++) bf[j] = Kt[d*64 + c0 + j];
            #pragma unroll
            for (int i = 0; i < 4; i++)
                #pragma unroll
                for (int j = 0; j < 4; j++) s[i][j] = fmaf(af[i], bf[j], s[i][j]);
        }

        #pragma unroll
        for (int i = 0; i < 4; i++) {
            int qr = q0 + r0 + i;
            float rm = -1e30f;
            #pragma unroll
            for (int j = 0; j < 4; j++) {
                float sv = s[i][j] * 0.125f;
                if (k0 + c0 + j > qr) sv = -1e9f;
                s[i][j] = sv;
                rm = fmaxf(rm, sv);
            }
            #pragma unroll
            for (int off = 1; off < 16; off <<= 1)
                rm = fmaxf(rm, __shfl_xor_sync(0xffffffffu, rm, off));
            float mold = Ms[r0 + i];
            float mnew = fmaxf(mold, rm);
            float pv[4], rsum = 0.f;
            #pragma unroll
            for (int j = 0; j < 4; j++) { pv[j] = expf(s[i][j] - mnew); rsum += pv[j]; }
            #pragma unroll
            for (int off = 1; off < 16; off <<= 1)
                rsum += __shfl_xor_sync(0xffffffffu, rsum, off);
            float sc = expf(mold - mnew);
            #pragma unroll
            for (int j = 0; j < 4; j++) acco[i][j] *= sc;
            if (tc == 0) { Ms[r0 + i] = mnew; Ls[r0 + i] = Ls[r0 + i] * sc + rsum; }
            #pragma unroll
            for (int j = 0; j < 4; j++) Pt[(c0 + j) * 64 + r0 + i] = pv[j];
        }
        __syncthreads();

        #pragma unroll 8
        for (int kk = 0; kk < 64; kk++) {
            float af[4], bf[4];
            #pragma unroll
            for (int i = 0; i < 4; i++) af[i] = Pt[kk*64 + r0 + i];
            #pragma unroll
            for (int j = 0; j < 4; j++) bf[j] = Vs[kk*64 + c0 + j];
            #pragma unroll
            for (int i = 0; i < 4; i++)
                #pragma unroll
                for (int j = 0; j < 4; j++) acco[i][j] = fmaf(af[i], bf[j], acco[i][j]);
        }
        __syncthreads();
    }

    #pragma unroll
    for (int i = 0; i < 4; i++) {
        float inv = 1.f / Ls[r0 + i];
        float4 ov = make_float4(acco[i][0]*inv, acco[i][1]*inv, acco[i][2]*inv, acco[i][3]*inv);
        *(float4*)(g_ao + headoff + (size_t)(q0 + r0 + i) * Dd + c0) = ov;
    }
}

// ----------------------------- output projection + residual -----------------
__global__ void __launch_bounds__(256) k_oproj(const float* __restrict__ wo,
                                               const float* __restrict__ x,
                                               float* __restrict__ out) {
    __shared__ float sm[4096];
    int m0 = blockIdx.y * 128, n0 = blockIdx.x * 128;
    float acc[8][8]; ZERO_ACC(acc);
    const float* aPtr = g_ao + (size_t)(m0 + (threadIdx.x >> 1)) * Dd;
    gemm_tile(aPtr, wo, Dd, n0, Dd, acc, sm, sm + 2048);
    int tm = (threadIdx.x >> 4) * 8, tn = (threadIdx.x & 15) * 8;
    #pragma unroll
    for (int i = 0; i < 8; i++) {
        size_t base = (size_t)(m0 + tm + i) * Dd + n0 + tn;
        float4 x0 = *(const float4*)(x + base);
        float4 x1 = *(const float4*)(x + base + 4);
        float4 r0 = make_float4(acc[i][0]+x0.x, acc[i][1]+x0.y, acc[i][2]+x0.z, acc[i][3]+x0.w);
        float4 r1 = make_float4(acc[i][4]+x1.x, acc[i][5]+x1.y, acc[i][6]+x1.z, acc[i][7]+x1.w);
        *(float4*)(g_h + base)     = r0;  *(float4*)(g_h + base + 4) = r1;
        *(float4*)(out + base)     = r0;  *(float4*)(out + base + 4) = r1;
    }
}

// ----------------------------- gating / top-2 routing -----------------------
__global__ void __launch_bounds__(256) k_gate(const float* __restrict__ gw) {
    int t = blockIdx.x, tid = threadIdx.x;
    float p[Ee];
    #pragma unroll
    for (int e = 0; e < Ee; e++) p[e] = 0.f;
    for (int d = tid; d < Dd; d += 256) {
        float xv = g_h2[(size_t)t * Dd + d];
        const float* grow = gw + (size_t)d * Ee;
        #pragma unroll
        for (int e = 0; e < Ee; e++) p[e] = fmaf(xv, grow[e], p[e]);
    }
    #pragma unroll
    for (int e = 0; e < Ee; e++)
        #pragma unroll
        for (int off = 16; off; off >>= 1)
            p[e] += __shfl_xor_sync(0xffffffffu, p[e], off);
    __shared__ float red[8][Ee];
    int warp = tid >> 5;
    if ((tid & 31) == 0)
        #pragma unroll
        for (int e = 0; e < Ee; e++) red[warp][e] = p[e];
    __syncthreads();
    if (tid == 0) {
        float lg[Ee], mx = -1e30f;
        #pragma unroll
        for (int e = 0; e < Ee; e++) {
            float s = 0.f;
            #pragma unroll
            for (int w = 0; w < 8; w++) s += red[w][e];
            lg[e] = s; mx = fmaxf(mx, s);
        }
        float pr[Ee], sum = 0.f;
        #pragma unroll
        for (int e = 0; e < Ee; e++) { pr[e] = expf(lg[e] - mx); sum += pr[e]; }
        #pragma unroll
        for (int e = 0; e < Ee; e++) pr[e] /= sum;
        int i1 = 0;
        #pragma unroll
        for (int e = 1; e < Ee; e++) if (pr[e] > pr[i1]) i1 = e;
        int i2 = (i1 == 0) ? 1 : 0;
        #pragma unroll
        for (int e = 0; e < Ee; e++) if (e != i1 && pr[e] > pr[i2]) i2 = e;
        float s2 = pr[i1] + pr[i2];
        float wa = pr[i1] / s2, wb = pr[i2] / s2;
        int pp = atomicAdd(&g_cnt[i1], 1);
        g_idx[i1 * Tt + pp] = t;  g_wgt[i1 * Tt + pp] = wa;
        pp = atomicAdd(&g_cnt[i2], 1);
        g_idx[i2 * Tt + pp] = t;  g_wgt[i2 * Tt + pp] = wb;
    }
}

// ----------------------------- MoE expert GEMMs (gathered) ------------------
__global__ void __launch_bounds__(256) k_ffn1(const float* __restrict__ w1) {
    __shared__ float sm[4096];
    int e = blockIdx.z;
    int c = g_cnt[e];
    int m0 = blockIdx.y * 128, n0 = blockIdx.x * 128;
    if (m0 >= c) return;
    int arow = m0 + (threadIdx.x >> 1);
    const float* aPtr = (arow < c) ? (g_h2 + (size_t)g_idx[e * Tt + arow] * Dd) : (const float*)0;
    float acc[8][8]; ZERO_ACC(acc);
    gemm_tile(aPtr, w1 + (size_t)e * Dd * Ff, Ff, n0, Dd, acc, sm, sm + 2048);
    int tm = (threadIdx.x >> 4) * 8, tn = (threadIdx.x & 15) * 8;
    #pragma unroll
    for (int i = 0; i < 8; i++) {
        int r = m0 + tm + i;
        if (r < c) {
            size_t base = ((size_t)e * Tt + r) * Ff + n0 + tn;
            *(float4*)(g_act + base)     = make_float4(acc[i][0], acc[i][1], acc[i][2], acc[i][3]);
            *(float4*)(g_act + base + 4) = make_float4(acc[i][4], acc[i][5], acc[i][6], acc[i][7]);
        }
    }
}

__global__ void __launch_bounds__(256) k_ffn3(const float* __restrict__ w3) {
    __shared__ float sm[4096];
    int e = blockIdx.z;
    int c = g_cnt[e];
    int m0 = blockIdx.y * 128, n0 = blockIdx.x * 128;
    if (m0 >= c) return;
    int arow = m0 + (threadIdx.x >> 1);
    const float* aPtr = (arow < c) ? (g_h2 + (size_t)g_idx[e * Tt + arow] * Dd) : (const float*)0;
    float acc[8][8]; ZERO_ACC(acc);
    gemm_tile(aPtr, w3 + (size_t)e * Dd * Ff, Ff, n0, Dd, acc, sm, sm + 2048);
    int tm = (threadIdx.x >> 4) * 8, tn = (threadIdx.x & 15) * 8;
    #pragma unroll
    for (int i = 0; i < 8; i++) {
        int r = m0 + tm + i;
        if (r < c) {
            size_t base = ((size_t)e * Tt + r) * Ff + n0 + tn;
            #pragma unroll
            for (int j = 0; j < 8; j++) {
                float raw = g_act[base + j];
                float sg  = 1.f / (1.f + expf(-raw));
                g_act[base + j] = raw * sg * acc[i][j];
            }
        }
    }
}

__global__ void __launch_bounds__(256) k_ffn2(const float* __restrict__ w2,
                                              float* __restrict__ out) {
    __shared__ float sm[4096];
    int e = blockIdx.z;
    int c = g_cnt[e];
    int m0 = blockIdx.y * 128, n0 = blockIdx.x * 128;
    if (m0 >= c) return;
    int arow = m0 + (threadIdx.x >> 1);
    const float* aPtr = (arow < c) ? (g_act + ((size_t)e * Tt + arow) * Ff) : (const float*)0;
    float acc[8][8]; ZERO_ACC(acc);
    gemm_tile(aPtr, w2 + (size_t)e * Ff * Dd, Dd, n0, Ff, acc, sm, sm + 2048);
    int tm = (threadIdx.x >> 4) * 8, tn = (threadIdx.x & 15) * 8;
    #pragma unroll
    for (int i = 0; i < 8; i++) {
        int r = m0 + tm + i;
        if (r < c) {
            int t = g_idx[e * Tt + r];
            float wg = g_wgt[e * Tt + r];
            size_t base = (size_t)t * Dd + n0 + tn;
            #pragma unroll
            for (int j = 0; j < 8; j++)
                atomicAdd(&out[base + j], wg * acc[i][j]);
        }
    }
}

// ----------------------------- launch ---------------------------------------
extern "C" void kernel_launch(void* const* d_in, const int* in_sizes, int n_in,
                              void* d_out, int out_size) {
    const float* x   = (const float*)d_in[0];
    const int*   pos = (const int*)  d_in[1];
    const float* ln1 = (const float*)d_in[2];
    const float* ln2 = (const float*)d_in[3];
    const float* wq  = (const float*)d_in[4];
    const float* wk  = (const float*)d_in[5];
    const float* wv  = (const float*)d_in[6];
    const float* wo  = (const float*)d_in[7];
    const float* gw  = (const float*)d_in[8];
    const float* w1  = (const float*)d_in[9];
    const float* w3  = (const float*)d_in[10];
    const float* w2  = (const float*)d_in[11];
    float* out = (float*)d_out;

    const int ATTN_SMEM = (4 * 4096 + 128) * (int)sizeof(float);   // 66048 B
    cudaFuncSetAttribute(k_attn, cudaFuncAttributeMaxDynamicSharedMemorySize, ATTN_SMEM);

    k_zero<<<1, 32>>>();
    k_rms <<<Tt, 256>>>(x, ln1, 0);                        // g_h1 = rmsnorm(x)
    k_qkv <<<dim3(8, 32, 3), 256>>>(wq, wk, wv);           // q,k,v
    k_rope<<<(Tt * Hh * 32) / 256, 256>>>(pos);            // rope(q,k) in place
    k_attn<<<dim3(32, 32), 256, ATTN_SMEM>>>();            // g_ao
    k_oproj<<<dim3(8, 32), 256>>>(wo, x, out);             // g_h = out = x + ao@wo
    k_rms <<<Tt, 256>>>(nullptr, ln2, 1);                  // g_h2 = rmsnorm(g_h)
    k_gate<<<Tt, 256>>>(gw);                               // routing lists
    k_ffn1<<<dim3(32, 32, 8), 256>>>(w1);                  // act = Xe @ w1[e]
    k_ffn3<<<dim3(32, 32, 8), 256>>>(w3);                  // act = silu(act)*(Xe@w3[e])
    k_ffn2<<<dim3(8, 32, 8), 256>>>(w2, out);              // out += wgt * act@w2[e]
}